// round 6
// baseline (speedup 1.0000x reference)
#include <cuda_runtime.h>
#include <cuda_fp16.h>
#include <cstdint>

// Problem constants
#define N_ROWS   32768
#define D_DIM    512
#define C_BOOKS  64
#define K_CODES  16
#define M_OUT    128
#define NODES    15

// Scratch
__device__ __align__(16) uint32_t g_codes[N_ROWS * 8];               // 4-bit codes
__device__ __align__(16) __half   g_Lf16[M_OUT * C_BOOKS * K_CODES]; // L fp16 [m][1024]

// ---------------------------------------------------------------------------
// PTX helpers (sm_103 baseline — harness ptxas targets sm_103, no tcgen05)
// ---------------------------------------------------------------------------
__device__ __forceinline__ uint32_t smem_u32(const void* p) {
    uint32_t a;
    asm("{ .reg .u64 t; cvta.to.shared.u64 t, %1; cvt.u32.u64 %0, t; }" : "=r"(a) : "l"(p));
    return a;
}
__device__ __forceinline__ void cp16(uint32_t dst, const void* src) {
    asm volatile("cp.async.cg.shared.global [%0], [%1], 16;" :: "r"(dst), "l"(src) : "memory");
}
#define CP_COMMIT() asm volatile("cp.async.commit_group;" ::: "memory")
#define CP_WAIT(n)  asm volatile("cp.async.wait_group %0;" :: "n"(n) : "memory")

__device__ __forceinline__ void ldsm4(uint32_t& r0, uint32_t& r1, uint32_t& r2,
                                      uint32_t& r3, uint32_t addr) {
    asm volatile("ldmatrix.sync.aligned.m8n8.x4.shared.b16 {%0,%1,%2,%3}, [%4];"
                 : "=r"(r0), "=r"(r1), "=r"(r2), "=r"(r3) : "r"(addr));
}
__device__ __forceinline__ void mma16816(float* c, uint32_t a0, uint32_t a1,
                                         uint32_t a2, uint32_t a3,
                                         uint32_t b0, uint32_t b1) {
    asm volatile("mma.sync.aligned.m16n8k16.row.col.f32.f16.f16.f32 "
                 "{%0,%1,%2,%3}, {%4,%5,%6,%7}, {%8,%9}, {%0,%1,%2,%3};"
                 : "+f"(c[0]), "+f"(c[1]), "+f"(c[2]), "+f"(c[3])
                 : "r"(a0), "r"(a1), "r"(a2), "r"(a3), "r"(b0), "r"(b1));
}

// ---------------------------------------------------------------------------
// Kernel 1: encode (32 rows/CTA, 512 threads) + fused L->fp16 convert.
// ---------------------------------------------------------------------------
#define ENC_ROWS    32
#define ENC_THREADS 512
#define ROW_PAD     516

__global__ __launch_bounds__(ENC_THREADS)
void encode_kernel(const float* __restrict__ I,
                   const float* __restrict__ T,
                   const int*   __restrict__ dims,
                   const float* __restrict__ L)
{
    extern __shared__ float sm[];
    float* Ir = sm;                              // 32 * 516
    float* Ts = sm + ENC_ROWS * ROW_PAD;         // 960
    int*   ds = (int*)(Ts + 960);                // 256

    const int tid = threadIdx.x;
    const int nb  = blockIdx.x * ENC_ROWS;
    const uint32_t sbase = smem_u32(sm);

    // cp.async staging of 32 rows (4096 x 16B)
    const char* src = (const char*)(I + (size_t)nb * D_DIM);
    #pragma unroll
    for (int i = 0; i < 8; i++) {
        int q = tid + ENC_THREADS * i;
        int r = q >> 7;              // 128 x 16B per row
        int j = q & 127;
        cp16(sbase + (uint32_t)(r * (ROW_PAD * 4) + j * 16),
             src + (size_t)r * (D_DIM * 4) + j * 16);
    }
    CP_COMMIT();

    // Fused convert: first 128 CTAs each convert 256 float4 of L -> g_Lf16
    if (blockIdx.x < 128 && tid < 256) {
        int q = blockIdx.x * 256 + tid;
        float4 v = ((const float4*)L)[q];
        ((__half2*)g_Lf16)[q * 2]     = __floats2half2_rn(v.x, v.y);
        ((__half2*)g_Lf16)[q * 2 + 1] = __floats2half2_rn(v.z, v.w);
    }

    for (int i = tid; i < 960; i += ENC_THREADS) Ts[i] = T[i];
    if (tid < 256) ds[tid] = dims[tid];

    CP_WAIT(0);
    __syncthreads();

    const int r  = tid >> 4;        // row 0..31
    const int cg = tid & 15;        // 4 codebooks: c = cg*4 + j
    const float* row = Ir + r * ROW_PAD;

    uint32_t pack = 0;
    #pragma unroll
    for (int j = 0; j < 4; j++) {
        const int c = cg * 4 + j;
        const int*   dp = ds + c * 4;
        const float* tp = Ts + c * NODES;
        const float v0 = row[dp[0]];
        const float v1 = row[dp[1]];
        const float v2 = row[dp[2]];
        const float v3 = row[dp[3]];
        int p;
        p = (v0 > tp[0]) ? 1 : 0;
        p = (p << 1) | ((v1 > tp[1 + p]) ? 1 : 0);
        p = (p << 1) | ((v2 > tp[3 + p]) ? 1 : 0);
        p = (p << 1) | ((v3 > tp[7 + p]) ? 1 : 0);
        pack |= ((uint32_t)p) << (4 * j);
    }
    ((uint16_t*)g_codes)[(size_t)(nb + r) * 16 + cg] = (uint16_t)pack;
}

// ---------------------------------------------------------------------------
// Kernel 2: tensor aggregation (mma.sync m16n8k16).
// CTA: 128 rows x 64 m (grid.y=2 covers M=128). 4 warps: warp = 64 rows x 32 m
// -> acc 64 regs; __launch_bounds__(128,4) => 4 CTAs/SM, 16 warps.
// B chunk (64 m x 128 k fp16) triple-buffered via cp.async, 1 sync per chunk.
// A one-hot synthesized in registers from 4-bit codes.
// ---------------------------------------------------------------------------
#define AGG_THREADS 128
#define NTILE       128
#define MTILE       64
#define BROW        272                         // 256B data + 16B pad per m-row
#define BTILE_B     (MTILE * BROW)              // 17408
#define SM_BUF      4096
#define SM_AGG      (SM_BUF + 3 * BTILE_B)      // 56320

__global__ __launch_bounds__(AGG_THREADS, 4)
void agg_kernel(float* __restrict__ out)
{
    extern __shared__ __align__(16) char smem[];
    const uint32_t sb = smem_u32(smem);
    const int tid  = threadIdx.x;
    const int wid  = tid >> 5;
    const int lane = tid & 31;
    const int g    = lane >> 2;     // 0..7
    const int tg   = lane & 3;      // 0..3
    const int n0   = blockIdx.x * NTILE;
    const int mg0  = blockIdx.y * MTILE;        // global m offset of this CTA

    // Stage codes: 128 rows * 32B = 256 uint4
    {
        const uint4* srcc = (const uint4*)(g_codes + (size_t)n0 * 8);
        uint4* dst = (uint4*)smem;
        dst[tid]       = srcc[tid];
        dst[tid + 128] = srcc[tid + 128];
    }

    // ldmatrix per-lane constant offset (validated layout)
    const int t = lane >> 3;
    const uint32_t lane_m   = (uint32_t)(((t >> 1) * 8) + (lane & 7));
    const uint32_t lane_off = lane_m * BROW + (uint32_t)((t & 1) * 16);

    const int rbase = (wid & 1) * 64;    // warp rows within CTA
    const int mwarp = (wid >> 1) * 32;   // warp m within CTA

    // stage chunk 'c' into buffer buf: 64 m-rows x 16 segs of 16B
    const char* srcL = (const char*)g_Lf16 + (size_t)mg0 * 2048;
    #define STAGE(c, buf)                                                        \
        do {                                                                     \
            const uint32_t bdst = sb + SM_BUF + (buf) * BTILE_B;                 \
            const char* s = srcL + (c) * 256;                                    \
            _Pragma("unroll")                                                    \
            for (int i = 0; i < 8; i++) {                                        \
                int q = tid + AGG_THREADS * i;                                   \
                int m = q >> 4, seg = q & 15;                                    \
                cp16(bdst + (uint32_t)(m * BROW + seg * 16),                     \
                     s + (size_t)m * 2048 + seg * 16);                           \
            }                                                                    \
            CP_COMMIT();                                                         \
        } while (0)

    STAGE(0, 0);
    STAGE(1, 1);

    float acc[4][4][4];
    #pragma unroll
    for (int rt = 0; rt < 4; rt++)
        #pragma unroll
        for (int nb = 0; nb < 4; nb++)
            #pragma unroll
            for (int i = 0; i < 4; i++) acc[rt][nb][i] = 0.f;

    const uint32_t* cs = (const uint32_t*)smem;

    #pragma unroll 1
    for (int ch = 0; ch < 8; ch++) {
        if (ch < 7) { CP_WAIT(1); } else { CP_WAIT(0); }
        __syncthreads();
        if (ch + 2 < 8) { STAGE(ch + 2, (ch + 2) % 3); }

        const uint32_t bbase = sb + SM_BUF + (ch % 3) * BTILE_B
                             + (uint32_t)mwarp * BROW + lane_off;

        // code words: 4 row-tiles x (row g, row g+8)
        uint32_t wlo[4], whi[4];
        #pragma unroll
        for (int rt = 0; rt < 4; rt++) {
            wlo[rt] = cs[(rbase + 16 * rt + g)     * 8 + ch];
            whi[rt] = cs[(rbase + 16 * rt + g + 8) * 8 + ch];
        }

        #pragma unroll
        for (int kbl = 0; kbl < 8; kbl++) {
            // B fragments: 32 m = two 16-m ldmatrix.x4
            uint32_t b[2][4];
            #pragma unroll
            for (int p = 0; p < 2; p++) {
                ldsm4(b[p][0], b[p][1], b[p][2], b[p][3],
                      bbase + (uint32_t)(kbl * 32) + (uint32_t)(p * 16 * BROW));
            }
            #pragma unroll
            for (int rt = 0; rt < 4; rt++) {
                const uint32_t klo = (wlo[rt] >> (4 * kbl)) & 15u;
                const uint32_t khi = (whi[rt] >> (4 * kbl)) & 15u;
                const uint32_t hlo = 0x3C00u << ((klo & 1u) << 4);
                const uint32_t hhi = 0x3C00u << ((khi & 1u) << 4);
                const uint32_t slo = klo >> 1, shi = khi >> 1;
                const uint32_t A0 = (slo == (uint32_t)tg)     ? hlo : 0u;
                const uint32_t A1 = (shi == (uint32_t)tg)     ? hhi : 0u;
                const uint32_t A2 = (slo == (uint32_t)tg + 4) ? hlo : 0u;
                const uint32_t A3 = (shi == (uint32_t)tg + 4) ? hhi : 0u;
                #pragma unroll
                for (int p = 0; p < 2; p++) {
                    mma16816(acc[rt][2 * p],     A0, A1, A2, A3, b[p][0], b[p][1]);
                    mma16816(acc[rt][2 * p + 1], A0, A1, A2, A3, b[p][2], b[p][3]);
                }
            }
        }
        __syncwarp();
    }

    // Epilogue: STG.64 pairs
    #pragma unroll
    for (int rt = 0; rt < 4; rt++) {
        const int rowA = n0 + rbase + 16 * rt + g;
        #pragma unroll
        for (int nb = 0; nb < 4; nb++) {
            float2 lo = make_float2(acc[rt][nb][0], acc[rt][nb][1]);
            float2 hi = make_float2(acc[rt][nb][2], acc[rt][nb][3]);
            *(float2*)(out + (size_t)rowA * M_OUT + mg0 + mwarp + nb * 8 + tg * 2)       = lo;
            *(float2*)(out + (size_t)(rowA + 8) * M_OUT + mg0 + mwarp + nb * 8 + tg * 2) = hi;
        }
    }
}

// ---------------------------------------------------------------------------
extern "C" void kernel_launch(void* const* d_in, const int* in_sizes, int n_in,
                              void* d_out, int out_size)
{
    (void)in_sizes; (void)n_in; (void)out_size;
    const float* I    = (const float*)d_in[0];
    const float* T    = (const float*)d_in[1];
    const float* L    = (const float*)d_in[2];
    const int*   dims = (const int*)d_in[5];
    float* out = (float*)d_out;

    const int encSmem = (ENC_ROWS * ROW_PAD + 960 + 256) * 4;  // 70912
    cudaFuncSetAttribute(encode_kernel, cudaFuncAttributeMaxDynamicSharedMemorySize, encSmem);
    cudaFuncSetAttribute(agg_kernel,    cudaFuncAttributeMaxDynamicSharedMemorySize, SM_AGG);

    encode_kernel<<<N_ROWS / ENC_ROWS, ENC_THREADS, encSmem>>>(I, T, dims, L);
    agg_kernel<<<dim3(N_ROWS / NTILE, M_OUT / MTILE), AGG_THREADS, SM_AGG>>>(out);
}

// round 7
// speedup vs baseline: 1.0982x; 1.0982x over previous
#include <cuda_runtime.h>
#include <cuda_fp16.h>
#include <cstdint>

// Problem constants
#define N_ROWS   32768
#define D_DIM    512
#define C_BOOKS  64
#define K_CODES  16
#define M_OUT    128
#define NODES    15

// Scratch
__device__ __align__(16) uint32_t g_codes[N_ROWS * 8];               // 4-bit codes
__device__ __align__(16) __half   g_Lf16[M_OUT * C_BOOKS * K_CODES]; // L fp16 [m][1024]

// ---------------------------------------------------------------------------
// PTX helpers (sm_103 baseline — harness ptxas targets sm_103, no tcgen05)
// ---------------------------------------------------------------------------
__device__ __forceinline__ uint32_t smem_u32(const void* p) {
    uint32_t a;
    asm("{ .reg .u64 t; cvta.to.shared.u64 t, %1; cvt.u32.u64 %0, t; }" : "=r"(a) : "l"(p));
    return a;
}
__device__ __forceinline__ void cp16(uint32_t dst, const void* src) {
    asm volatile("cp.async.cg.shared.global [%0], [%1], 16;" :: "r"(dst), "l"(src) : "memory");
}
#define CP_COMMIT() asm volatile("cp.async.commit_group;" ::: "memory")
#define CP_WAIT(n)  asm volatile("cp.async.wait_group %0;" :: "n"(n) : "memory")

__device__ __forceinline__ void ldsm4(uint32_t& r0, uint32_t& r1, uint32_t& r2,
                                      uint32_t& r3, uint32_t addr) {
    asm volatile("ldmatrix.sync.aligned.m8n8.x4.shared.b16 {%0,%1,%2,%3}, [%4];"
                 : "=r"(r0), "=r"(r1), "=r"(r2), "=r"(r3) : "r"(addr));
}
__device__ __forceinline__ void mma16816(float* c, uint32_t a0, uint32_t a1,
                                         uint32_t a2, uint32_t a3,
                                         uint32_t b0, uint32_t b1) {
    asm volatile("mma.sync.aligned.m16n8k16.row.col.f32.f16.f16.f32 "
                 "{%0,%1,%2,%3}, {%4,%5,%6,%7}, {%8,%9}, {%0,%1,%2,%3};"
                 : "+f"(c[0]), "+f"(c[1]), "+f"(c[2]), "+f"(c[3])
                 : "r"(a0), "r"(a1), "r"(a2), "r"(a3), "r"(b0), "r"(b1));
}

// ---------------------------------------------------------------------------
// Kernel 1: encode (16 rows/CTA, 256 threads — fastest measured config)
// + fused L->fp16 convert in first 128 CTAs.
// ---------------------------------------------------------------------------
#define ENC_ROWS    16
#define ENC_THREADS 256
#define ROW_PAD     516

__global__ __launch_bounds__(ENC_THREADS)
void encode_kernel(const float* __restrict__ I,
                   const float* __restrict__ T,
                   const int*   __restrict__ dims,
                   const float* __restrict__ L)
{
    extern __shared__ float sm[];
    float* Ir = sm;
    float* Ts = sm + ENC_ROWS * ROW_PAD;
    int*   ds = (int*)(Ts + 960);

    const int tid = threadIdx.x;
    const int nb  = blockIdx.x * ENC_ROWS;
    const uint32_t sbase = smem_u32(sm);

    // cp.async staging of 16 rows (2048 x 16B)
    const char* src = (const char*)(I + (size_t)nb * D_DIM);
    #pragma unroll
    for (int i = 0; i < 8; i++) {
        int q = tid + ENC_THREADS * i;
        int r = q >> 7;
        int j = q & 127;
        cp16(sbase + (uint32_t)(r * (ROW_PAD * 4) + j * 16),
             src + (size_t)r * (D_DIM * 4) + j * 16);
    }
    CP_COMMIT();

    // Fused convert: first 128 CTAs each convert 256 float4 of L -> g_Lf16
    if (blockIdx.x < 128) {
        int q = blockIdx.x * 256 + tid;
        float4 v = ((const float4*)L)[q];
        ((__half2*)g_Lf16)[q * 2]     = __floats2half2_rn(v.x, v.y);
        ((__half2*)g_Lf16)[q * 2 + 1] = __floats2half2_rn(v.z, v.w);
    }

    for (int i = tid; i < 960; i += ENC_THREADS) Ts[i] = T[i];
    ds[tid] = dims[tid];

    CP_WAIT(0);
    __syncthreads();

    const int r  = tid >> 4;
    const int cg = tid & 15;
    const float* row = Ir + r * ROW_PAD;

    uint32_t pack = 0;
    #pragma unroll
    for (int j = 0; j < 4; j++) {
        const int c = cg * 4 + j;
        const int*   dp = ds + c * 4;
        const float* tp = Ts + c * NODES;
        const float v0 = row[dp[0]];
        const float v1 = row[dp[1]];
        const float v2 = row[dp[2]];
        const float v3 = row[dp[3]];
        int p;
        p = (v0 > tp[0]) ? 1 : 0;
        p = (p << 1) | ((v1 > tp[1 + p]) ? 1 : 0);
        p = (p << 1) | ((v2 > tp[3 + p]) ? 1 : 0);
        p = (p << 1) | ((v3 > tp[7 + p]) ? 1 : 0);
        pack |= ((uint32_t)p) << (4 * j);
    }
    ((uint16_t*)g_codes)[(size_t)(nb + r) * 16 + cg] = (uint16_t)pack;
}

// ---------------------------------------------------------------------------
// Kernel 2: tensor aggregation (mma.sync m16n8k16).
// CTA: 128 rows x 128 m, 256 threads = 8 warps as 4(n) x 2(m):
// warp = 32 rows x 64 m -> acc[2][8][4] = 64 regs, no spills, 2 CTAs/SM.
// B chunk (128 m x 128 k fp16) double-buffered via cp.async, 1 sync/chunk.
// A one-hot synthesized in registers from 4-bit codes.
// ---------------------------------------------------------------------------
#define AGG_THREADS 256
#define NTILE       128
#define BROW        272                         // 256B data + 16B pad per m-row
#define BTILE_B     (128 * BROW)                // 34816
#define SM_BUF      4096
#define SM_AGG      (SM_BUF + 2 * BTILE_B)      // 73728

__global__ __launch_bounds__(AGG_THREADS, 2)
void agg_kernel(float* __restrict__ out)
{
    extern __shared__ __align__(16) char smem[];
    const uint32_t sb = smem_u32(smem);
    const int tid  = threadIdx.x;
    const int wid  = tid >> 5;
    const int lane = tid & 31;
    const int g    = lane >> 2;     // 0..7
    const int tg   = lane & 3;      // 0..3
    const int n0   = blockIdx.x * NTILE;

    // Stage codes: 128 rows * 32B = 256 uint4
    {
        const uint4* srcc = (const uint4*)(g_codes + (size_t)n0 * 8);
        ((uint4*)smem)[tid] = srcc[tid];
    }

    // ldmatrix per-lane constant offset (validated layout)
    const int t = lane >> 3;
    const uint32_t lane_m   = (uint32_t)(((t >> 1) * 8) + (lane & 7));
    const uint32_t lane_off = lane_m * BROW + (uint32_t)((t & 1) * 16);

    const int rbase = (wid & 3) * 32;    // warp rows within CTA
    const int mwarp = (wid >> 2) * 64;   // warp m within CTA

    // stage chunk 'c' (128 m x 128 k) into buffer buf
    const char* srcL = (const char*)g_Lf16;
    #define STAGE(c, buf)                                                        \
        do {                                                                     \
            const uint32_t bdst = sb + SM_BUF + (buf) * BTILE_B;                 \
            const char* s = srcL + (c) * 256;                                    \
            _Pragma("unroll")                                                    \
            for (int i = 0; i < 8; i++) {                                        \
                int q = tid + AGG_THREADS * i;                                   \
                int m = q >> 4, seg = q & 15;                                    \
                cp16(bdst + (uint32_t)(m * BROW + seg * 16),                     \
                     s + (size_t)m * 2048 + seg * 16);                           \
            }                                                                    \
            CP_COMMIT();                                                         \
        } while (0)

    STAGE(0, 0);

    float acc[2][8][4];
    #pragma unroll
    for (int rt = 0; rt < 2; rt++)
        #pragma unroll
        for (int nb = 0; nb < 8; nb++)
            #pragma unroll
            for (int i = 0; i < 4; i++) acc[rt][nb][i] = 0.f;

    const uint32_t* cs = (const uint32_t*)smem;

    #pragma unroll 1
    for (int ch = 0; ch < 8; ch++) {
        CP_WAIT(0);
        __syncthreads();
        if (ch < 7) { STAGE(ch + 1, (ch + 1) & 1); }   // overlaps with consume

        const uint32_t bbase = sb + SM_BUF + (ch & 1) * BTILE_B
                             + (uint32_t)mwarp * BROW + lane_off;

        // code words: 2 row-tiles x (row g, row g+8)
        uint32_t wlo[2], whi[2];
        #pragma unroll
        for (int rt = 0; rt < 2; rt++) {
            wlo[rt] = cs[(rbase + 16 * rt + g)     * 8 + ch];
            whi[rt] = cs[(rbase + 16 * rt + g + 8) * 8 + ch];
        }

        #pragma unroll
        for (int kbl = 0; kbl < 8; kbl++) {
            // B fragments: 64 m = four 16-m ldmatrix.x4
            uint32_t b[4][4];
            #pragma unroll
            for (int p = 0; p < 4; p++) {
                ldsm4(b[p][0], b[p][1], b[p][2], b[p][3],
                      bbase + (uint32_t)(kbl * 32) + (uint32_t)(p * 16 * BROW));
            }
            #pragma unroll
            for (int rt = 0; rt < 2; rt++) {
                const uint32_t klo = (wlo[rt] >> (4 * kbl)) & 15u;
                const uint32_t khi = (whi[rt] >> (4 * kbl)) & 15u;
                const uint32_t hlo = 0x3C00u << ((klo & 1u) << 4);
                const uint32_t hhi = 0x3C00u << ((khi & 1u) << 4);
                const uint32_t slo = klo >> 1, shi = khi >> 1;
                const uint32_t A0 = (slo == (uint32_t)tg)     ? hlo : 0u;
                const uint32_t A1 = (shi == (uint32_t)tg)     ? hhi : 0u;
                const uint32_t A2 = (slo == (uint32_t)tg + 4) ? hlo : 0u;
                const uint32_t A3 = (shi == (uint32_t)tg + 4) ? hhi : 0u;
                #pragma unroll
                for (int p = 0; p < 4; p++) {
                    mma16816(acc[rt][2 * p],     A0, A1, A2, A3, b[p][0], b[p][1]);
                    mma16816(acc[rt][2 * p + 1], A0, A1, A2, A3, b[p][2], b[p][3]);
                }
            }
        }
    }

    // Epilogue: STG.64 pairs
    #pragma unroll
    for (int rt = 0; rt < 2; rt++) {
        const int rowA = n0 + rbase + 16 * rt + g;
        #pragma unroll
        for (int nb = 0; nb < 8; nb++) {
            float2 lo = make_float2(acc[rt][nb][0], acc[rt][nb][1]);
            float2 hi = make_float2(acc[rt][nb][2], acc[rt][nb][3]);
            *(float2*)(out + (size_t)rowA * M_OUT + mwarp + nb * 8 + tg * 2)       = lo;
            *(float2*)(out + (size_t)(rowA + 8) * M_OUT + mwarp + nb * 8 + tg * 2) = hi;
        }
    }
}

// ---------------------------------------------------------------------------
extern "C" void kernel_launch(void* const* d_in, const int* in_sizes, int n_in,
                              void* d_out, int out_size)
{
    (void)in_sizes; (void)n_in; (void)out_size;
    const float* I    = (const float*)d_in[0];
    const float* T    = (const float*)d_in[1];
    const float* L    = (const float*)d_in[2];
    const int*   dims = (const int*)d_in[5];
    float* out = (float*)d_out;

    const int encSmem = (ENC_ROWS * ROW_PAD + 960 + 256) * 4;  // 37888
    cudaFuncSetAttribute(encode_kernel, cudaFuncAttributeMaxDynamicSharedMemorySize, encSmem);
    cudaFuncSetAttribute(agg_kernel,    cudaFuncAttributeMaxDynamicSharedMemorySize, SM_AGG);

    encode_kernel<<<N_ROWS / ENC_ROWS, ENC_THREADS, encSmem>>>(I, T, dims, L);
    agg_kernel<<<N_ROWS / NTILE, AGG_THREADS, SM_AGG>>>(out);
}